// round 13
// baseline (speedup 1.0000x reference)
#include <cuda_runtime.h>
#include <cuda_fp16.h>
#include <cstdint>

// ---------------------------------------------------------------------------
// y[b,s,o] = sum_i x[b,s,i]*w[o,i] + bias[o],  w = (q-128)*scale (Q8_0)
// dtypes: x f32 [4,1024,4096], q i32 [4096,128,32], scales f32, bias f32
// -> out f32.  GEMM: A=x [M,K] f16, B=w [N,K] f16 (col-major for row.col),
// C [M,N] f32.  compute_103: no tcgen05 -> mma.sync + cp.async.
// R13: tile 128x64 (2048 CTAs -> wave-quantization loss 13.5% -> 1.2%),
// 4 warps (2x2) of 64x32, 3-stage cp.async, SW128 smem, 2 CTA/SM.
// ---------------------------------------------------------------------------

#define MAX_O 4096
#define MAX_K 4096
#define MAX_M 4096

__device__ __half g_w[(size_t)MAX_O * MAX_K];  // dequantized weights [N,K]
__device__ __half g_x[(size_t)MAX_M * MAX_K];  // f16 activations    [M,K]

// ---------------------------------------------------------------------------
// Merged prep: x f32->f16 and q i32->f16 dequant in one launch.
// ---------------------------------------------------------------------------
__global__ void prep_kernel(const float* __restrict__ x,
                            const int* __restrict__ q,
                            const float* __restrict__ scales,
                            int nx_chunks, int O, int K) {
    int idx = blockIdx.x * blockDim.x + threadIdx.x;
    if (idx < nx_chunks) {
        size_t i = (size_t)idx * 8;
        const float4* xp = reinterpret_cast<const float4*>(x + i);
        float4 a = xp[0], b = xp[1];
        __half h[8];
        h[0] = __float2half(a.x); h[1] = __float2half(a.y);
        h[2] = __float2half(a.z); h[3] = __float2half(a.w);
        h[4] = __float2half(b.x); h[5] = __float2half(b.y);
        h[6] = __float2half(b.z); h[7] = __float2half(b.w);
        *reinterpret_cast<float4*>(&g_x[i]) = *reinterpret_cast<const float4*>(h);
        return;
    }
    int c = idx - nx_chunks;
    int chunks_per_row = K >> 3;
    if (c >= O * chunks_per_row) return;
    int o  = c / chunks_per_row;
    int k0 = (c - o * chunks_per_row) << 3;
    int nb = k0 >> 5;
    float s = scales[o * (K >> 5) + nb];

    const int4* qp = reinterpret_cast<const int4*>(q + (size_t)o * K + k0);
    int4 q0 = qp[0];
    int4 q1 = qp[1];

    __half h[8];
    h[0] = __float2half((float)(q0.x - 128) * s);
    h[1] = __float2half((float)(q0.y - 128) * s);
    h[2] = __float2half((float)(q0.z - 128) * s);
    h[3] = __float2half((float)(q0.w - 128) * s);
    h[4] = __float2half((float)(q1.x - 128) * s);
    h[5] = __float2half((float)(q1.y - 128) * s);
    h[6] = __float2half((float)(q1.z - 128) * s);
    h[7] = __float2half((float)(q1.w - 128) * s);

    *reinterpret_cast<float4*>(&g_w[(size_t)o * K + k0]) =
        *reinterpret_cast<const float4*>(h);
}

// ---------------------------------------------------------------------------
// GEMM: mma.sync m16n8k16, CTA 128x64x64, 4 warps (2x2) of 64x32 tiles,
// 3-stage cp.async, SW128 smem, double-buffered ldmatrix, rasterized grid.
// ---------------------------------------------------------------------------
constexpr int BM = 128, BN = 64, BK = 64;
constexpr int THREADS = 128;
constexpr int STAGES = 3;

constexpr int A_BYTES = BM * 128;                 // 16 KB
constexpr int B_BYTES = BN * 128;                 // 8 KB
constexpr int STAGE_BYTES = A_BYTES + B_BYTES;    // 24 KB
constexpr int SM_BIAS = 0;                        // BN f32 = 256 B
constexpr int SM_TILES = 1024;
constexpr int SMEM_TOTAL = SM_TILES + STAGES * STAGE_BYTES;  // ~73 KB

__device__ __forceinline__ uint32_t smem_u32(const void* p) {
    uint32_t a;
    asm("{ .reg .u64 t; cvta.to.shared.u64 t, %1; cvt.u32.u64 %0, t; }"
        : "=r"(a) : "l"(p));
    return a;
}
__device__ __forceinline__ uint32_t sw128(uint32_t off) {
    return off ^ ((off >> 3) & 0x70);
}
__device__ __forceinline__ void cp16(uint32_t saddr, const void* gaddr) {
    asm volatile("cp.async.cg.shared.global [%0], [%1], 16;"
                 :: "r"(saddr), "l"(gaddr));
}
__device__ __forceinline__ void cp_commit() {
    asm volatile("cp.async.commit_group;" ::: "memory");
}
__device__ __forceinline__ void cp_wait1() {
    asm volatile("cp.async.wait_group 1;" ::: "memory");
}
__device__ __forceinline__ void ldmx4(uint32_t* r, uint32_t addr) {
    asm volatile("ldmatrix.sync.aligned.m8n8.x4.shared.b16 {%0,%1,%2,%3}, [%4];"
                 : "=r"(r[0]), "=r"(r[1]), "=r"(r[2]), "=r"(r[3]) : "r"(addr));
}
__device__ __forceinline__ void mma16816(float* c, const uint32_t* a,
                                         const uint32_t* b) {
    asm volatile(
        "mma.sync.aligned.m16n8k16.row.col.f32.f16.f16.f32 "
        "{%0,%1,%2,%3}, {%4,%5,%6,%7}, {%8,%9}, {%0,%1,%2,%3};"
        : "+f"(c[0]), "+f"(c[1]), "+f"(c[2]), "+f"(c[3])
        : "r"(a[0]), "r"(a[1]), "r"(a[2]), "r"(a[3]), "r"(b[0]), "r"(b[1]));
}

__global__ void __launch_bounds__(THREADS, 2)
gemm_mma_kernel(const float* __restrict__ bias,
                float* __restrict__ C, int M, int N, int K) {
    extern __shared__ char smem[];
    const uint32_t sb_tiles = smem_u32(smem + SM_TILES);
    const int tid  = threadIdx.x;
    const int wid  = tid >> 5;
    const int lane = tid & 31;

    // Threadblock rasterization: GROUP M-tiles per N-column sweep (L2 reuse)
    const int nbx = gridDim.x;            // N tiles (64)
    const int nby = gridDim.y;            // M tiles (32)
    int bid = blockIdx.y * nbx + blockIdx.x;
    constexpr int GROUP = 16;
    int tiles_per_group = GROUP * nbx;
    int g    = bid / tiles_per_group;
    int rem  = bid - g * tiles_per_group;
    int gm   = g * GROUP;
    int gsz  = (nby - gm) < GROUP ? (nby - gm) : GROUP;
    const int bm = (gm + rem % gsz) * BM;
    const int bn = (rem / gsz) * BN;

    const int wm_off = (wid >> 1) * 64;   // 0 or 64
    const int wn_off = (wid & 1) * 32;    // 0 or 32

    float* bias_s = (float*)(smem + SM_BIAS);
    if (tid < BN) bias_s[tid] = bias[bn + tid];

    const __half* Ag = g_x + (size_t)bm * K;
    const __half* Bg = g_w + (size_t)bn * K;

    const int lr = tid >> 3;        // base row 0..15 (stride 16)
    const int lc = (tid & 7) * 8;   // element offset within 64-wide k-row

    auto load_stage = [&](int stage, int kblk) {
        uint32_t a_s = sb_tiles + stage * STAGE_BYTES;
        uint32_t b_s = a_s + A_BYTES;
#pragma unroll
        for (int i = 0; i < 8; i++) {                 // A: 128 rows
            int r = lr + i * 16;
            cp16(a_s + sw128(r * 128 + lc * 2), Ag + (size_t)r * K + kblk + lc);
        }
#pragma unroll
        for (int i = 0; i < 4; i++) {                 // B: 64 rows
            int r = lr + i * 16;
            cp16(b_s + sw128(r * 128 + lc * 2), Bg + (size_t)r * K + kblk + lc);
        }
        cp_commit();
    };

    float acc[4][4][4];
#pragma unroll
    for (int mi = 0; mi < 4; mi++)
#pragma unroll
        for (int ni = 0; ni < 4; ni++)
#pragma unroll
            for (int e = 0; e < 4; e++) acc[mi][ni][e] = 0.0f;

    load_stage(0, 0);
    load_stage(1, BK);

    const int iters = K / BK;     // 64

    // ldmatrix lane addressing
    const int a_row_l = lane & 15;
    const int a_chk_l = lane >> 4;               // 0..1
    const int b_row_l = (lane & 7) + ((lane >> 4) << 3);
    const int b_chk_l = (lane >> 3) & 1;

    uint32_t afrag[2][4][4];
    uint32_t bfrag[2][2][4];

    for (int it = 0; it < iters; ++it) {
        cp_wait1();
        __syncthreads();

        if (it + STAGES - 1 < iters)
            load_stage((it + STAGES - 1) % STAGES, (it + STAGES - 1) * BK);
        else
            cp_commit();  // keep group counting aligned

        uint32_t a_s = sb_tiles + (it % STAGES) * STAGE_BYTES;
        uint32_t b_s = a_s + A_BYTES;

        // Prefetch ks=0 fragments
#pragma unroll
        for (int mi = 0; mi < 4; mi++) {
            int row = wm_off + mi * 16 + a_row_l;
            ldmx4(afrag[0][mi], a_s + sw128(row * 128 + a_chk_l * 16));
        }
#pragma unroll
        for (int nj = 0; nj < 2; nj++) {
            int row = wn_off + nj * 16 + b_row_l;
            ldmx4(bfrag[0][nj], b_s + sw128(row * 128 + b_chk_l * 16));
        }

#pragma unroll
        for (int ks = 0; ks < BK / 16; ks++) {
            const int cur = ks & 1;
            if (ks < BK / 16 - 1) {
                const int nxt = cur ^ 1;
#pragma unroll
                for (int mi = 0; mi < 4; mi++) {
                    int row = wm_off + mi * 16 + a_row_l;
                    ldmx4(afrag[nxt][mi],
                          a_s + sw128(row * 128 + (ks + 1) * 32 + a_chk_l * 16));
                }
#pragma unroll
                for (int nj = 0; nj < 2; nj++) {
                    int row = wn_off + nj * 16 + b_row_l;
                    ldmx4(bfrag[nxt][nj],
                          b_s + sw128(row * 128 + (ks + 1) * 32 + b_chk_l * 16));
                }
            }
#pragma unroll
            for (int mi = 0; mi < 4; mi++)
#pragma unroll
                for (int ni = 0; ni < 4; ni++)
                    mma16816(acc[mi][ni], afrag[cur][mi],
                             &bfrag[cur][ni >> 1][(ni & 1) * 2]);
        }
    }

    // Epilogue: registers -> global, fused bias, float2 stores
#pragma unroll
    for (int mi = 0; mi < 4; mi++) {
        int r0 = bm + wm_off + mi * 16 + (lane >> 2);
#pragma unroll
        for (int ni = 0; ni < 4; ni++) {
            int col  = wn_off + ni * 8 + (lane & 3) * 2;
            float b0 = bias_s[col], b1 = bias_s[col + 1];
            float2 v0 = make_float2(acc[mi][ni][0] + b0, acc[mi][ni][1] + b1);
            float2 v1 = make_float2(acc[mi][ni][2] + b0, acc[mi][ni][3] + b1);
            *reinterpret_cast<float2*>(C + (size_t)r0 * N + bn + col) = v0;
            *reinterpret_cast<float2*>(C + (size_t)(r0 + 8) * N + bn + col) = v1;
        }
    }
}

// ---------------------------------------------------------------------------
// Launch
// ---------------------------------------------------------------------------
extern "C" void kernel_launch(void* const* d_in, const int* in_sizes, int n_in,
                              void* d_out, int out_size) {
    const float* x      = (const float*)d_in[0];
    const int*   q      = (const int*)  d_in[1];
    const float* scales = (const float*)d_in[2];
    const float* bias   = (const float*)d_in[3];
    float*       out    = (float*)d_out;

    const int O = in_sizes[3];                 // 4096
    const int K = in_sizes[1] / O;             // 4096
    const int M = in_sizes[0] / K;             // 4096
    const int N = O;

    int nx_chunks = (int)((size_t)M * K / 8);
    int nq_chunks = O * (K >> 3);
    int total = nx_chunks + nq_chunks;
    prep_kernel<<<(total + 255) / 256, 256>>>(x, q, scales, nx_chunks, O, K);

    cudaFuncSetAttribute(gemm_mma_kernel,
                         cudaFuncAttributeMaxDynamicSharedMemorySize, SMEM_TOTAL);
    dim3 grid(N / BN, M / BM);
    gemm_mma_kernel<<<grid, THREADS, SMEM_TOTAL>>>(bias, out, M, N, K);
}

// round 15
// speedup vs baseline: 1.1536x; 1.1536x over previous
#include <cuda_runtime.h>
#include <cuda_fp16.h>
#include <cstdint>

// ---------------------------------------------------------------------------
// y[b,s,o] = sum_i x[b,s,i]*w[o,i] + bias[o],  w = (q-128)*scale (Q8_0)
// dtypes: x f32 [4,1024,4096], q i32 [4096,128,32], scales f32, bias f32
// -> out f32.  GEMM: A=x [M,K] f16, B=w [N,K] f16 (col-major for row.col),
// C [M,N] f32.  compute_103: no tcgen05 -> mma.sync + cp.async.
// R15: R14 mbarrier pipeline with the deadlock fixed: cp.async.mbarrier.
// arrive must be .noinc (default variant nets zero against the expected
// count -> phase never completes -> R14 hang).
// ---------------------------------------------------------------------------

#define MAX_O 4096
#define MAX_K 4096
#define MAX_M 4096

__device__ __half g_w[(size_t)MAX_O * MAX_K];  // dequantized weights [N,K]
__device__ __half g_x[(size_t)MAX_M * MAX_K];  // f16 activations    [M,K]

// ---------------------------------------------------------------------------
// Merged prep: x f32->f16 and q i32->f16 dequant in one launch.
// ---------------------------------------------------------------------------
__global__ void prep_kernel(const float* __restrict__ x,
                            const int* __restrict__ q,
                            const float* __restrict__ scales,
                            int nx_chunks, int O, int K) {
    int idx = blockIdx.x * blockDim.x + threadIdx.x;
    if (idx < nx_chunks) {
        size_t i = (size_t)idx * 8;
        const float4* xp = reinterpret_cast<const float4*>(x + i);
        float4 a = xp[0], b = xp[1];
        __half h[8];
        h[0] = __float2half(a.x); h[1] = __float2half(a.y);
        h[2] = __float2half(a.z); h[3] = __float2half(a.w);
        h[4] = __float2half(b.x); h[5] = __float2half(b.y);
        h[6] = __float2half(b.z); h[7] = __float2half(b.w);
        *reinterpret_cast<float4*>(&g_x[i]) = *reinterpret_cast<const float4*>(h);
        return;
    }
    int c = idx - nx_chunks;
    int chunks_per_row = K >> 3;
    if (c >= O * chunks_per_row) return;
    int o  = c / chunks_per_row;
    int k0 = (c - o * chunks_per_row) << 3;
    int nb = k0 >> 5;
    float s = scales[o * (K >> 5) + nb];

    const int4* qp = reinterpret_cast<const int4*>(q + (size_t)o * K + k0);
    int4 q0 = qp[0];
    int4 q1 = qp[1];

    __half h[8];
    h[0] = __float2half((float)(q0.x - 128) * s);
    h[1] = __float2half((float)(q0.y - 128) * s);
    h[2] = __float2half((float)(q0.z - 128) * s);
    h[3] = __float2half((float)(q0.w - 128) * s);
    h[4] = __float2half((float)(q1.x - 128) * s);
    h[5] = __float2half((float)(q1.y - 128) * s);
    h[6] = __float2half((float)(q1.z - 128) * s);
    h[7] = __float2half((float)(q1.w - 128) * s);

    *reinterpret_cast<float4*>(&g_w[(size_t)o * K + k0]) =
        *reinterpret_cast<const float4*>(h);
}

// ---------------------------------------------------------------------------
// GEMM: mma.sync m16n8k16, CTA 128x128x64, 4 warps (2x2) of 64x64 tiles,
// 3-stage cp.async with mbarrier full/empty pipeline, SW128 smem, raster.
// ---------------------------------------------------------------------------
constexpr int BM = 128, BN = 128, BK = 64;
constexpr int THREADS = 128;
constexpr int STAGES = 3;

constexpr int TILE_BYTES  = BM * 128;             // 16 KB each (A and B)
constexpr int STAGE_BYTES = 2 * TILE_BYTES;       // 32 KB
constexpr int SM_MBAR = 0;                        // full[3] @0,8,16; empty[3] @24,32,40
constexpr int SM_BIAS = 64;                       // BN f32 = 512 B
constexpr int SM_TILES = 1024;
constexpr int SMEM_TOTAL = SM_TILES + STAGES * STAGE_BYTES;  // 97.5 KB

__device__ __forceinline__ uint32_t smem_u32(const void* p) {
    uint32_t a;
    asm("{ .reg .u64 t; cvta.to.shared.u64 t, %1; cvt.u32.u64 %0, t; }"
        : "=r"(a) : "l"(p));
    return a;
}
__device__ __forceinline__ uint32_t sw128(uint32_t off) {
    return off ^ ((off >> 3) & 0x70);
}
__device__ __forceinline__ void cp16(uint32_t saddr, const void* gaddr) {
    asm volatile("cp.async.cg.shared.global [%0], [%1], 16;"
                 :: "r"(saddr), "l"(gaddr));
}
__device__ __forceinline__ void mbar_init(uint32_t addr, uint32_t cnt) {
    asm volatile("mbarrier.init.shared.b64 [%0], %1;"
                 :: "r"(addr), "r"(cnt) : "memory");
}
__device__ __forceinline__ void mbar_arrive(uint32_t addr) {
    asm volatile("mbarrier.arrive.shared.b64 _, [%0];" :: "r"(addr) : "memory");
}
// Arrive (count 1, NO expected-count increment) when all of this thread's
// prior cp.asyncs complete. .noinc is load-bearing: the default variant
// increments pending by 1 at issue (net zero) and the phase never completes.
__device__ __forceinline__ void cp_arrive_noinc(uint32_t addr) {
    asm volatile("cp.async.mbarrier.arrive.noinc.shared.b64 [%0];"
                 :: "r"(addr) : "memory");
}
__device__ __forceinline__ void mbar_wait(uint32_t addr, uint32_t parity) {
    asm volatile(
        "{\n\t"
        ".reg .pred P;\n\t"
        "LAB_W_%=:\n\t"
        "mbarrier.try_wait.parity.acquire.cta.shared::cta.b64 P, [%0], %1, 0x989680;\n\t"
        "@P bra LAB_D_%=;\n\t"
        "bra LAB_W_%=;\n\t"
        "LAB_D_%=:\n\t"
        "}"
        :: "r"(addr), "r"(parity) : "memory");
}
__device__ __forceinline__ void ldmx4(uint32_t* r, uint32_t addr) {
    asm volatile("ldmatrix.sync.aligned.m8n8.x4.shared.b16 {%0,%1,%2,%3}, [%4];"
                 : "=r"(r[0]), "=r"(r[1]), "=r"(r[2]), "=r"(r[3]) : "r"(addr));
}
__device__ __forceinline__ void mma16816(float* c, const uint32_t* a,
                                         const uint32_t* b) {
    asm volatile(
        "mma.sync.aligned.m16n8k16.row.col.f32.f16.f16.f32 "
        "{%0,%1,%2,%3}, {%4,%5,%6,%7}, {%8,%9}, {%0,%1,%2,%3};"
        : "+f"(c[0]), "+f"(c[1]), "+f"(c[2]), "+f"(c[3])
        : "r"(a[0]), "r"(a[1]), "r"(a[2]), "r"(a[3]), "r"(b[0]), "r"(b[1]));
}

__global__ void __launch_bounds__(THREADS, 2)
gemm_mma_kernel(const float* __restrict__ bias,
                float* __restrict__ C, int M, int N, int K) {
    extern __shared__ char smem[];
    const uint32_t sb       = smem_u32(smem);
    const uint32_t sb_tiles = sb + SM_TILES;
    const int tid  = threadIdx.x;
    const int wid  = tid >> 5;
    const int lane = tid & 31;

    // Threadblock rasterization: GROUP M-tiles per N-column sweep (L2 reuse)
    const int nbx = gridDim.x;
    const int nby = gridDim.y;
    int bid = blockIdx.y * nbx + blockIdx.x;
    constexpr int GROUP = 16;
    int tiles_per_group = GROUP * nbx;
    int g    = bid / tiles_per_group;
    int rem  = bid - g * tiles_per_group;
    int gm   = g * GROUP;
    int gsz  = (nby - gm) < GROUP ? (nby - gm) : GROUP;
    const int bm = (gm + rem % gsz) * BM;
    const int bn = (rem / gsz) * BN;

    const int wm_off = (wid >> 1) * 64;   // 0 or 64
    const int wn_off = (wid & 1) * 64;    // 0 or 64

    // mbarriers: full[s] = sb + SM_MBAR + s*8, empty[s] = +24 + s*8
    if (tid == 0) {
#pragma unroll
        for (int s = 0; s < STAGES; s++) {
            mbar_init(sb + SM_MBAR + s * 8, THREADS);        // full
            mbar_init(sb + SM_MBAR + 24 + s * 8, THREADS);   // empty
        }
    }
    __syncthreads();

    float* bias_s = (float*)(smem + SM_BIAS);
    if (tid < BN) bias_s[tid] = bias[bn + tid];

    const __half* Ag = g_x + (size_t)bm * K;
    const __half* Bg = g_w + (size_t)bn * K;

    const int lr = tid >> 3;        // base row 0..15 (stride 16)
    const int lc = (tid & 7) * 8;   // element offset within 64-wide k-row

    // Fill a stage: 16 cp.asyncs then noinc cp-arrive on full[stage].
    auto fill_stage = [&](int stage, int kblk) {
        uint32_t a_s = sb_tiles + stage * STAGE_BYTES;
        uint32_t b_s = a_s + TILE_BYTES;
#pragma unroll
        for (int i = 0; i < 8; i++) {
            int r = lr + i * 16;
            cp16(a_s + sw128(r * 128 + lc * 2), Ag + (size_t)r * K + kblk + lc);
        }
#pragma unroll
        for (int i = 0; i < 8; i++) {
            int r = lr + i * 16;
            cp16(b_s + sw128(r * 128 + lc * 2), Bg + (size_t)r * K + kblk + lc);
        }
        cp_arrive_noinc(sb + SM_MBAR + stage * 8);
    };

    float acc[4][8][4];
#pragma unroll
    for (int mi = 0; mi < 4; mi++)
#pragma unroll
        for (int ni = 0; ni < 8; ni++)
#pragma unroll
            for (int e = 0; e < 4; e++) acc[mi][ni][e] = 0.0f;

    // Producer cursor (empty-waits): starts phase 1 (first waits pass).
    int p_stage = 0, p_phase = 1;
    // Consumer cursor (full-waits): starts phase 0.
    int c_stage = 0, c_phase = 0;

    // Prologue: fill stages 0 and 1 (itf = 0, 1)
#pragma unroll
    for (int itf = 0; itf < 2; itf++) {
        mbar_wait(sb + SM_MBAR + 24 + p_stage * 8, p_phase);   // passes
        fill_stage(p_stage, itf * BK);
        if (++p_stage == STAGES) { p_stage = 0; p_phase ^= 1; }
    }

    const int iters = K / BK;     // 64

    // ldmatrix lane addressing
    const int a_row_l = lane & 15;
    const int a_chk_l = lane >> 4;               // 0..1
    const int b_row_l = (lane & 7) + ((lane >> 4) << 3);
    const int b_chk_l = (lane >> 3) & 1;

    uint32_t afrag[2][4][4];
    uint32_t bfrag[2][4][4];

    for (int it = 0; it < iters; ++it) {
        mbar_wait(sb + SM_MBAR + c_stage * 8, c_phase);   // full[cur]

        uint32_t a_s = sb_tiles + c_stage * STAGE_BYTES;
        uint32_t b_s = a_s + TILE_BYTES;

        // Prefetch ks=0 fragments
#pragma unroll
        for (int mi = 0; mi < 4; mi++) {
            int row = wm_off + mi * 16 + a_row_l;
            ldmx4(afrag[0][mi], a_s + sw128(row * 128 + a_chk_l * 16));
        }
#pragma unroll
        for (int nj = 0; nj < 4; nj++) {
            int row = wn_off + nj * 16 + b_row_l;
            ldmx4(bfrag[0][nj], b_s + sw128(row * 128 + b_chk_l * 16));
        }

#pragma unroll
        for (int ks = 0; ks < BK / 16; ks++) {
            const int cur = ks & 1;
            if (ks < BK / 16 - 1) {
                const int nxt = cur ^ 1;
#pragma unroll
                for (int mi = 0; mi < 4; mi++) {
                    int row = wm_off + mi * 16 + a_row_l;
                    ldmx4(afrag[nxt][mi],
                          a_s + sw128(row * 128 + (ks + 1) * 32 + a_chk_l * 16));
                }
#pragma unroll
                for (int nj = 0; nj < 4; nj++) {
                    int row = wn_off + nj * 16 + b_row_l;
                    ldmx4(bfrag[nxt][nj],
                          b_s + sw128(row * 128 + (ks + 1) * 32 + b_chk_l * 16));
                }
            }
#pragma unroll
            for (int mi = 0; mi < 4; mi++)
#pragma unroll
                for (int ni = 0; ni < 8; ni++)
                    mma16816(acc[mi][ni], afrag[cur][mi],
                             &bfrag[cur][ni >> 1][(ni & 1) * 2]);
        }

        // Done reading stage cur -> release it.
        mbar_arrive(sb + SM_MBAR + 24 + c_stage * 8);
        if (++c_stage == STAGES) { c_stage = 0; c_phase ^= 1; }

        // Fill stage for iteration it+2.
        if (it + 2 < iters) {
            mbar_wait(sb + SM_MBAR + 24 + p_stage * 8, p_phase);
            fill_stage(p_stage, (it + 2) * BK);
            if (++p_stage == STAGES) { p_stage = 0; p_phase ^= 1; }
        }
    }

    // Epilogue: registers -> global, fused bias, float2 stores
#pragma unroll
    for (int mi = 0; mi < 4; mi++) {
        int r0 = bm + wm_off + mi * 16 + (lane >> 2);
#pragma unroll
        for (int ni = 0; ni < 8; ni++) {
            int col  = wn_off + ni * 8 + (lane & 3) * 2;
            float b0 = bias_s[col], b1 = bias_s[col + 1];
            float2 v0 = make_float2(acc[mi][ni][0] + b0, acc[mi][ni][1] + b1);
            float2 v1 = make_float2(acc[mi][ni][2] + b0, acc[mi][ni][3] + b1);
            *reinterpret_cast<float2*>(C + (size_t)r0 * N + bn + col) = v0;
            *reinterpret_cast<float2*>(C + (size_t)(r0 + 8) * N + bn + col) = v1;
        }
    }
}

// ---------------------------------------------------------------------------
// Launch
// ---------------------------------------------------------------------------
extern "C" void kernel_launch(void* const* d_in, const int* in_sizes, int n_in,
                              void* d_out, int out_size) {
    const float* x      = (const float*)d_in[0];
    const int*   q      = (const int*)  d_in[1];
    const float* scales = (const float*)d_in[2];
    const float* bias   = (const float*)d_in[3];
    float*       out    = (float*)d_out;

    const int O = in_sizes[3];                 // 4096
    const int K = in_sizes[1] / O;             // 4096
    const int M = in_sizes[0] / K;             // 4096
    const int N = O;

    int nx_chunks = (int)((size_t)M * K / 8);
    int nq_chunks = O * (K >> 3);
    int total = nx_chunks + nq_chunks;
    prep_kernel<<<(total + 255) / 256, 256>>>(x, q, scales, nx_chunks, O, K);

    cudaFuncSetAttribute(gemm_mma_kernel,
                         cudaFuncAttributeMaxDynamicSharedMemorySize, SMEM_TOTAL);
    dim3 grid(N / BN, M / BM);
    gemm_mma_kernel<<<grid, THREADS, SMEM_TOTAL>>>(bias, out, M, N, K);
}